// round 1
// baseline (speedup 1.0000x reference)
#include <cuda_runtime.h>
#include <math.h>

// Problem constants: B=16, C=256, H=W=64, M=512
#define NROWS 65536          // B*H*W
#define CDIM  256
#define MDIM  512
#define ODIM  256
#define HWDIM 4096
#define K2DIM 512            // 2*C

// ---------------- scratch (device globals; no allocation) ----------------
__device__ float g_qn[NROWS * CDIM];            // normalized query, [N, C]
__device__ float g_E[(size_t)NROWS * MDIM];     // exp(score), [N, M]
__device__ float g_cm[NROWS * CDIM];            // concat_memory, [N, C]
__device__ float g_yraw[NROWS * ODIM];          // pre-BN conv output, [B, O, H, W] layout
__device__ float g_rinv[NROWS];                 // 1 / row-sum of E
__device__ float g_colpart[256 * MDIM];         // partial column sums
__device__ float g_cinv[MDIM];                  // 1 / col-sum of E
__device__ float g_mean[ODIM];
__device__ float g_rstd[ODIM];

// ---------------- K1: channel-normalize + transpose to [N, C] ----------------
// 32 spatial positions per block; gather strided channels through smem.
__global__ void k_norm(const float* __restrict__ q) {
    __shared__ float s[256][33];
    __shared__ float red[8][32];
    __shared__ float invs[32];
    int n0 = blockIdx.x * 32;
    int b  = n0 >> 12;          // 4096 positions per batch image
    int hw0 = n0 & 4095;
    const float* base = q + (size_t)b * CDIM * HWDIM + hw0;
    for (int idx = threadIdx.x; idx < 256 * 32; idx += 256) {
        int c = idx >> 5, j = idx & 31;
        s[c][j] = base[c * HWDIM + j];             // coalesced over j
    }
    __syncthreads();
    int j = threadIdx.x & 31, g = threadIdx.x >> 5;
    float p = 0.f;
    #pragma unroll 8
    for (int c = g; c < 256; c += 8) { float v = s[c][j]; p += v * v; }
    red[g][j] = p;
    __syncthreads();
    if (threadIdx.x < 32) {
        float t = 0.f;
        #pragma unroll
        for (int gg = 0; gg < 8; gg++) t += red[gg][threadIdx.x];
        float nm = sqrtf(t);
        invs[threadIdx.x] = 1.0f / fmaxf(nm, 1e-12f);
    }
    __syncthreads();
    for (int idx = threadIdx.x; idx < 256 * 32; idx += 256) {
        int jj = idx >> 8, c = idx & 255;
        g_qn[(n0 + jj) * 256 + c] = s[c][jj] * invs[jj];   // coalesced over c
    }
}

// ---------------- GEMM1 (NT): E = exp(qn[N,256] @ mem[M,256]^T) ----------------
__global__ __launch_bounds__(256, 2) void k_gemm1(const float* __restrict__ Bm) {
    __shared__ float As[8][128];
    __shared__ float Bs[8][128];
    int m0 = blockIdx.x * 128;   // grid.x = 4
    int n0 = blockIdx.y * 128;   // grid.y = 512
    int tid = threadIdx.x;
    int tx = tid & 15, ty = tid >> 4;
    float acc[8][8] = {};
    int lr = tid >> 1;
    int lc = (tid & 1) * 4;
    const float* Aptr = g_qn + (size_t)(n0 + lr) * 256 + lc;
    const float* Bptr = Bm   + (size_t)(m0 + lr) * 256 + lc;
    for (int k0 = 0; k0 < 256; k0 += 8) {
        float4 av = *(const float4*)(Aptr + k0);
        float4 bv = *(const float4*)(Bptr + k0);
        As[lc + 0][lr] = av.x; As[lc + 1][lr] = av.y; As[lc + 2][lr] = av.z; As[lc + 3][lr] = av.w;
        Bs[lc + 0][lr] = bv.x; Bs[lc + 1][lr] = bv.y; Bs[lc + 2][lr] = bv.z; Bs[lc + 3][lr] = bv.w;
        __syncthreads();
        #pragma unroll
        for (int k = 0; k < 8; k++) {
            float a[8], b[8];
            *(float4*)(a)     = *(const float4*)&As[k][ty * 8];
            *(float4*)(a + 4) = *(const float4*)&As[k][ty * 8 + 4];
            *(float4*)(b)     = *(const float4*)&Bs[k][tx * 8];
            *(float4*)(b + 4) = *(const float4*)&Bs[k][tx * 8 + 4];
            #pragma unroll
            for (int i = 0; i < 8; i++)
                #pragma unroll
                for (int jj = 0; jj < 8; jj++)
                    acc[i][jj] += a[i] * b[jj];
        }
        __syncthreads();
    }
    #pragma unroll
    for (int i = 0; i < 8; i++) {
        int n = n0 + ty * 8 + i;
        float* dst = g_E + (size_t)n * 512 + m0 + tx * 8;
        float4 v0 = make_float4(expf(acc[i][0]), expf(acc[i][1]), expf(acc[i][2]), expf(acc[i][3]));
        float4 v1 = make_float4(expf(acc[i][4]), expf(acc[i][5]), expf(acc[i][6]), expf(acc[i][7]));
        *(float4*)dst = v0;
        *(float4*)(dst + 4) = v1;
    }
}

// ---------------- row sums of E: rinv[n] = 1/sum_m E[n][m] ----------------
__global__ void k_rowsum() {
    int warp = threadIdx.x >> 5, lane = threadIdx.x & 31;
    int n = blockIdx.x * 8 + warp;
    const float4* row = (const float4*)(g_E + (size_t)n * 512);
    float s = 0.f;
    #pragma unroll
    for (int idx = lane; idx < 128; idx += 32) {
        float4 v = row[idx];
        s += (v.x + v.y) + (v.z + v.w);
    }
    #pragma unroll
    for (int off = 16; off; off >>= 1) s += __shfl_xor_sync(0xffffffffu, s, off);
    if (lane == 0) g_rinv[n] = 1.0f / s;
}

// ---------------- column sums of E (deterministic two-stage) ----------------
__global__ void k_colpart() {
    int m = threadIdx.x;          // 512 threads
    int bi = blockIdx.x;          // 256 blocks, 256 rows each
    const float* p = g_E + (size_t)bi * 256 * 512 + m;
    float s = 0.f;
    #pragma unroll 8
    for (int r = 0; r < 256; r++) s += p[(size_t)r * 512];
    g_colpart[bi * 512 + m] = s;
}

__global__ void k_colfin() {
    int m = threadIdx.x;          // 512 threads, 1 block
    float s = 0.f;
    #pragma unroll 8
    for (int b = 0; b < 256; b++) s += g_colpart[b * 512 + m];
    g_cinv[m] = 1.0f / s;
}

// ---------------- write both softmax outputs ----------------
__global__ void k_soft(float* __restrict__ ssq, float* __restrict__ ssm) {
    int idx = blockIdx.x * blockDim.x + threadIdx.x;   // float4 index
    size_t e0 = (size_t)idx * 4;
    int n = (int)(e0 >> 9);
    int m = (int)(e0 & 511);
    float4 E4 = *(const float4*)(g_E + e0);
    float rv = g_rinv[n];
    float4 sm = make_float4(E4.x * rv, E4.y * rv, E4.z * rv, E4.w * rv);
    float4 sq = make_float4(E4.x * g_cinv[m], E4.y * g_cinv[m + 1],
                            E4.z * g_cinv[m + 2], E4.w * g_cinv[m + 3]);
    *(float4*)(ssm + e0) = sm;
    *(float4*)(ssq + e0) = sq;
}

// ---------------- GEMM2 (NN): cm = rinv[n] * (E[N,512] @ mem[512,256]) ----------------
__global__ __launch_bounds__(256, 2) void k_gemm2(const float* __restrict__ Bm) {
    __shared__ float As[8][128];
    __shared__ float Bs[8][128];
    int c0 = blockIdx.x * 128;   // grid.x = 2
    int n0 = blockIdx.y * 128;   // grid.y = 512
    int tid = threadIdx.x;
    int tx = tid & 15, ty = tid >> 4;
    float acc[8][8] = {};
    int lr = tid >> 1, lc = (tid & 1) * 4;
    int br = tid >> 5, bc = (tid & 31) * 4;
    const float* Aptr  = g_E + (size_t)(n0 + lr) * 512 + lc;
    const float* Bbase = Bm + c0 + bc;
    for (int k0 = 0; k0 < 512; k0 += 8) {
        float4 av = *(const float4*)(Aptr + k0);
        float4 bv = *(const float4*)(Bbase + (size_t)(k0 + br) * 256);
        As[lc + 0][lr] = av.x; As[lc + 1][lr] = av.y; As[lc + 2][lr] = av.z; As[lc + 3][lr] = av.w;
        *(float4*)&Bs[br][bc] = bv;
        __syncthreads();
        #pragma unroll
        for (int k = 0; k < 8; k++) {
            float a[8], b[8];
            *(float4*)(a)     = *(const float4*)&As[k][ty * 8];
            *(float4*)(a + 4) = *(const float4*)&As[k][ty * 8 + 4];
            *(float4*)(b)     = *(const float4*)&Bs[k][tx * 8];
            *(float4*)(b + 4) = *(const float4*)&Bs[k][tx * 8 + 4];
            #pragma unroll
            for (int i = 0; i < 8; i++)
                #pragma unroll
                for (int jj = 0; jj < 8; jj++)
                    acc[i][jj] += a[i] * b[jj];
        }
        __syncthreads();
    }
    #pragma unroll
    for (int i = 0; i < 8; i++) {
        int n = n0 + ty * 8 + i;
        float rv = g_rinv[n];
        float* dst = g_cm + (size_t)n * 256 + c0 + tx * 8;
        float4 v0 = make_float4(acc[i][0] * rv, acc[i][1] * rv, acc[i][2] * rv, acc[i][3] * rv);
        float4 v1 = make_float4(acc[i][4] * rv, acc[i][5] * rv, acc[i][6] * rv, acc[i][7] * rv);
        *(float4*)dst = v0;
        *(float4*)(dst + 4) = v1;
    }
}

// ---------------- GEMM3 (NT, split-K A): yraw = [qn|cm] @ conv_w^T in BOHW layout ----------------
__global__ __launch_bounds__(256, 2) void k_gemm3(const float* __restrict__ W) {
    __shared__ float As[8][128];
    __shared__ float Bs[8][128];
    int o0 = blockIdx.x * 128;   // grid.x = 2
    int n0 = blockIdx.y * 128;   // grid.y = 512
    int tid = threadIdx.x;
    int tx = tid & 15, ty = tid >> 4;
    float acc[8][8] = {};
    int lr = tid >> 1, lc = (tid & 1) * 4;
    for (int k0 = 0; k0 < 512; k0 += 8) {
        const float* Aptr = (k0 < 256)
            ? (g_qn + (size_t)(n0 + lr) * 256 + k0 + lc)
            : (g_cm + (size_t)(n0 + lr) * 256 + (k0 - 256) + lc);
        float4 av = *(const float4*)Aptr;
        float4 bv = *(const float4*)(W + (size_t)(o0 + lr) * 512 + k0 + lc);
        As[lc + 0][lr] = av.x; As[lc + 1][lr] = av.y; As[lc + 2][lr] = av.z; As[lc + 3][lr] = av.w;
        Bs[lc + 0][lr] = bv.x; Bs[lc + 1][lr] = bv.y; Bs[lc + 2][lr] = bv.z; Bs[lc + 3][lr] = bv.w;
        __syncthreads();
        #pragma unroll
        for (int k = 0; k < 8; k++) {
            float a[8], b[8];
            *(float4*)(a)     = *(const float4*)&As[k][ty * 8];
            *(float4*)(a + 4) = *(const float4*)&As[k][ty * 8 + 4];
            *(float4*)(b)     = *(const float4*)&Bs[k][tx * 8];
            *(float4*)(b + 4) = *(const float4*)&Bs[k][tx * 8 + 4];
            #pragma unroll
            for (int i = 0; i < 8; i++)
                #pragma unroll
                for (int jj = 0; jj < 8; jj++)
                    acc[i][jj] += a[i] * b[jj];
        }
        __syncthreads();
    }
    // write transposed into [B, O, H*W] layout (128-row tile stays within one batch image)
    int b = n0 >> 12;
    int hwb = (n0 & 4095) + ty * 8;
    float* ybase = g_yraw + (size_t)b * (ODIM * HWDIM) + hwb;
    #pragma unroll
    for (int jj = 0; jj < 8; jj++) {
        int o = o0 + tx * 8 + jj;
        float4 v0 = make_float4(acc[0][jj], acc[1][jj], acc[2][jj], acc[3][jj]);
        float4 v1 = make_float4(acc[4][jj], acc[5][jj], acc[6][jj], acc[7][jj]);
        *(float4*)(ybase + (size_t)o * 4096)     = v0;
        *(float4*)(ybase + (size_t)o * 4096 + 4) = v1;
    }
}

// ---------------- per-channel BN statistics (deterministic, 1 block / channel) ----------------
__global__ void k_stats() {
    int o = blockIdx.x;
    __shared__ float ssum[256];
    __shared__ float ssq[256];
    float s = 0.f, q2 = 0.f;
    for (int t = threadIdx.x; t < 65536; t += 256) {
        int b = t >> 12, hw = t & 4095;
        float v = g_yraw[(size_t)b * (ODIM * HWDIM) + (size_t)o * 4096 + hw];
        s += v; q2 += v * v;
    }
    ssum[threadIdx.x] = s; ssq[threadIdx.x] = q2;
    __syncthreads();
    for (int off = 128; off; off >>= 1) {
        if (threadIdx.x < off) {
            ssum[threadIdx.x] += ssum[threadIdx.x + off];
            ssq[threadIdx.x]  += ssq[threadIdx.x + off];
        }
        __syncthreads();
    }
    if (threadIdx.x == 0) {
        float mean = ssum[0] * (1.0f / 65536.0f);
        float var  = ssq[0] * (1.0f / 65536.0f) - mean * mean;
        g_mean[o] = mean;
        g_rstd[o] = rsqrtf(var + 1e-5f);
    }
}

// ---------------- BN affine + ReLU ----------------
__global__ void k_bn(const float* __restrict__ gamma, const float* __restrict__ beta,
                     float* __restrict__ yout) {
    int idx = blockIdx.x * blockDim.x + threadIdx.x;   // float4 index
    size_t e0 = (size_t)idx * 4;
    int o = (int)((e0 >> 12) & 255);
    float4 v = *(const float4*)(g_yraw + e0);
    float sc = g_rstd[o] * gamma[o];
    float sh = beta[o] - g_mean[o] * sc;
    float4 r = make_float4(fmaxf(v.x * sc + sh, 0.f), fmaxf(v.y * sc + sh, 0.f),
                           fmaxf(v.z * sc + sh, 0.f), fmaxf(v.w * sc + sh, 0.f));
    *(float4*)(yout + e0) = r;
}

// ---------------- launch ----------------
extern "C" void kernel_launch(void* const* d_in, const int* in_sizes, int n_in,
                              void* d_out, int out_size) {
    const float* query = (const float*)d_in[0];   // [16,256,64,64]
    const float* mem   = (const float*)d_in[1];   // [512,256] (pre-normalized)
    const float* convw = (const float*)d_in[2];   // [256,512]
    const float* gamma = (const float*)d_in[3];   // [256]
    const float* beta  = (const float*)d_in[4];   // [256]

    float* out = (float*)d_out;
    float* y_out   = out;                               // 16,777,216
    float* ssq_out = out + 16777216;                    // 33,554,432
    float* ssm_out = out + 16777216 + 33554432;         // 33,554,432

    k_norm   <<<2048, 256>>>(query);
    k_gemm1  <<<dim3(4, 512), 256>>>(mem);
    k_rowsum <<<8192, 256>>>();
    k_colpart<<<256, 512>>>();
    k_colfin <<<1, 512>>>();
    k_soft   <<<32768, 256>>>(ssq_out, ssm_out);
    k_gemm2  <<<dim3(2, 512), 256>>>(mem);
    k_gemm3  <<<dim3(2, 512), 256>>>(convw);
    k_stats  <<<256, 256>>>();
    k_bn     <<<16384, 256>>>(gamma, beta, y_out);
}

// round 3
// speedup vs baseline: 2.0313x; 2.0313x over previous
#include <cuda_runtime.h>
#include <cuda_bf16.h>
#include <math.h>
#include <stdint.h>

// Problem constants: B=16, C=256, H=W=64, M=512
#define NROWS 65536
#define CDIM  256
#define MDIM  512
#define HWDIM 4096

// ---------------- scratch (device globals; no allocation) ----------------
__device__ __nv_bfloat16 g_qn_hi[NROWS * CDIM];
__device__ __nv_bfloat16 g_qn_lo[NROWS * CDIM];
__device__ __nv_bfloat16 g_E_hi[(size_t)NROWS * MDIM];
__device__ __nv_bfloat16 g_E_lo[(size_t)NROWS * MDIM];
__device__ __nv_bfloat16 g_cm_hi[NROWS * CDIM];
__device__ __nv_bfloat16 g_cm_lo[NROWS * CDIM];
__device__ __nv_bfloat16 g_mem_hi[MDIM * CDIM];
__device__ __nv_bfloat16 g_mem_lo[MDIM * CDIM];
__device__ __nv_bfloat16 g_mT_hi[CDIM * MDIM];
__device__ __nv_bfloat16 g_mT_lo[CDIM * MDIM];
__device__ __nv_bfloat16 g_w_hi[CDIM * MDIM];
__device__ __nv_bfloat16 g_w_lo[CDIM * MDIM];
__device__ float g_yraw[NROWS * CDIM];
__device__ float g_rowpart[4][NROWS];
__device__ float g_rinv[NROWS];
__device__ float g_colpart[256 * MDIM];
__device__ float g_cinv[MDIM];
__device__ float g_mean[256];
__device__ float g_rstd[256];

// ---------------- helpers ----------------
__device__ __forceinline__ uint32_t s2u(const void* p) {
    uint32_t a;
    asm("{ .reg .u64 t; cvta.to.shared.u64 t, %1; cvt.u32.u64 %0, t; }" : "=r"(a) : "l"(p));
    return a;
}
__device__ __forceinline__ void cp16(uint32_t s, const void* g) {
    asm volatile("cp.async.ca.shared.global [%0], [%1], 16;" :: "r"(s), "l"(g));
}
__device__ __forceinline__ void ldsm4(uint32_t* r, uint32_t addr) {
    asm volatile("ldmatrix.sync.aligned.m8n8.x4.shared.b16 {%0,%1,%2,%3}, [%4];"
                 : "=r"(r[0]), "=r"(r[1]), "=r"(r[2]), "=r"(r[3]) : "r"(addr));
}
__device__ __forceinline__ void mma_bf(float* d, const uint32_t* a, const uint32_t* b) {
    asm volatile(
        "mma.sync.aligned.m16n8k16.row.col.f32.bf16.bf16.f32 "
        "{%0,%1,%2,%3}, {%4,%5,%6,%7}, {%8,%9}, {%0,%1,%2,%3};"
        : "+f"(d[0]), "+f"(d[1]), "+f"(d[2]), "+f"(d[3])
        : "r"(a[0]), "r"(a[1]), "r"(a[2]), "r"(a[3]), "r"(b[0]), "r"(b[1]));
}
__device__ __forceinline__ uint32_t pack_bf2(__nv_bfloat16 a, __nv_bfloat16 b) {
    return ((uint32_t)__bfloat16_as_ushort(b) << 16) | (uint32_t)__bfloat16_as_ushort(a);
}
__device__ __forceinline__ void split_bf(float v, __nv_bfloat16& h, __nv_bfloat16& l) {
    h = __float2bfloat16(v);
    l = __float2bfloat16(v - __bfloat162float(h));
}

// ---------------- K1: channel-normalize + transpose, write bf16 hi/lo ----------------
__global__ void k_norm(const float* __restrict__ q) {
    __shared__ float s[256][33];
    __shared__ float red[8][32];
    __shared__ float invs[32];
    int n0 = blockIdx.x * 32;
    int b  = n0 >> 12;
    int hw0 = n0 & 4095;
    const float* base = q + (size_t)b * CDIM * HWDIM + hw0;
    for (int idx = threadIdx.x; idx < 256 * 32; idx += 256) {
        int c = idx >> 5, j = idx & 31;
        s[c][j] = base[c * HWDIM + j];
    }
    __syncthreads();
    int j = threadIdx.x & 31, g = threadIdx.x >> 5;
    float p = 0.f;
    #pragma unroll 8
    for (int c = g; c < 256; c += 8) { float v = s[c][j]; p += v * v; }
    red[g][j] = p;
    __syncthreads();
    if (threadIdx.x < 32) {
        float t = 0.f;
        #pragma unroll
        for (int gg = 0; gg < 8; gg++) t += red[gg][threadIdx.x];
        invs[threadIdx.x] = 1.0f / fmaxf(sqrtf(t), 1e-12f);
    }
    __syncthreads();
    for (int idx = threadIdx.x; idx < 256 * 32; idx += 256) {
        int jj = idx >> 8, c = idx & 255;
        float v = s[c][jj] * invs[jj];
        __nv_bfloat16 h, l; split_bf(v, h, l);
        size_t off = (size_t)(n0 + jj) * 256 + c;
        g_qn_hi[off] = h;
        g_qn_lo[off] = l;
    }
}

// ---------------- prep: mem / memT / conv_w hi-lo splits ----------------
__global__ void k_prep(const float* __restrict__ mem, const float* __restrict__ w) {
    int i = blockIdx.x * 256 + threadIdx.x;   // 131072
    float v = mem[i];
    __nv_bfloat16 h, l; split_bf(v, h, l);
    g_mem_hi[i] = h; g_mem_lo[i] = l;
    int m = i >> 8, c = i & 255;
    g_mT_hi[c * 512 + m] = h; g_mT_lo[c * 512 + m] = l;
    float wv = w[i];
    __nv_bfloat16 wh, wl; split_bf(wv, wh, wl);
    g_w_hi[i] = wh; g_w_lo[i] = wl;
}

// ---------------- mma.sync bf16x3 GEMM ----------------
// MODE 1: E = exp(qn @ mem^T)   [N,512], K=256, grid(4,512); fuses row partials
// MODE 2: cm = rinv*(E @ mT^T)  [N,256], K=512, grid(2,512)
// MODE 3: yraw = [qn|cm] @ w^T  [N,256], K=512, grid(2,512), BOHW transpose
#define LDA 40                       // halves per smem row (32 + 8 pad)
#define PLANE_B (128 * LDA * 2)      // 10240 bytes per plane tile
#define STAGE_B (4 * PLANE_B)        // Ah, Al, Bh, Bl
#define SMEM_DYN (2 * STAGE_B)       // 81920 bytes

template <int MODE>
__global__ __launch_bounds__(256, 1) void k_gemm_mma() {
    extern __shared__ __align__(16) char smem_raw[];
    uint32_t smem_u = s2u(smem_raw);
    float* Ts = (float*)smem_raw;                 // epilogue staging 128x132 fp32
    float* red = (float*)smem_raw + 17152;        // 256 floats for row sums

    int tid = threadIdx.x, lane = tid & 31, wid = tid >> 5;
    int warp_m = wid & 3, warp_n = wid >> 2;      // 4 x 2 warps, warp tile 32x64
    int n0 = blockIdx.y * 128;
    int m0 = blockIdx.x * 128;
    const int NITER = (MODE == 1) ? 8 : 16;

    const __nv_bfloat16 *Bh, *Bl; int bStride;
    if (MODE == 1)      { Bh = g_mem_hi; Bl = g_mem_lo; bStride = 256; }
    else if (MODE == 2) { Bh = g_mT_hi;  Bl = g_mT_lo;  bStride = 512; }
    else                { Bh = g_w_hi;   Bl = g_w_lo;   bStride = 512; }

    float acc[2][8][4];
    #pragma unroll
    for (int a = 0; a < 2; a++)
        #pragma unroll
        for (int b = 0; b < 8; b++)
            #pragma unroll
            for (int c = 0; c < 4; c++) acc[a][b][c] = 0.f;

    auto issue = [&](int kc) {
        const __nv_bfloat16 *Ah, *Al; int aStride, ak0;
        if (MODE == 1)      { Ah = g_qn_hi; Al = g_qn_lo; aStride = 256; ak0 = kc * 32; }
        else if (MODE == 2) { Ah = g_E_hi;  Al = g_E_lo;  aStride = 512; ak0 = kc * 32; }
        else {
            if (kc < 8) { Ah = g_qn_hi; Al = g_qn_lo; }
            else        { Ah = g_cm_hi; Al = g_cm_lo; }
            aStride = 256; ak0 = (kc & 7) * 32;
        }
        int bk0 = kc * 32;
        uint32_t sb = smem_u + (kc & 1) * STAGE_B;
        #pragma unroll
        for (int it = 0; it < 2; it++) {
            int i = tid + it * 256;
            int r = i >> 2, seg = i & 3;
            uint32_t so = sb + (uint32_t)(r * LDA + seg * 8) * 2;
            size_t aoff = (size_t)(n0 + r) * aStride + ak0 + seg * 8;
            size_t boff = (size_t)(m0 + r) * bStride + bk0 + seg * 8;
            cp16(so,               Ah + aoff);
            cp16(so + PLANE_B,     Al + aoff);
            cp16(so + 2 * PLANE_B, Bh + boff);
            cp16(so + 3 * PLANE_B, Bl + boff);
        }
        asm volatile("cp.async.commit_group;" ::: "memory");
    };

    issue(0);
    for (int kc = 0; kc < NITER; kc++) {
        __syncthreads();   // buffer (kc+1)&1 free (compute kc-1 done everywhere)
        if (kc + 1 < NITER) {
            issue(kc + 1);
            asm volatile("cp.async.wait_group 1;" ::: "memory");
        } else {
            asm volatile("cp.async.wait_group 0;" ::: "memory");
        }
        __syncthreads();

        uint32_t sbase = smem_u + (kc & 1) * STAGE_B;
        #pragma unroll
        for (int ki = 0; ki < 2; ki++) {
            uint32_t a_h[2][4], a_l[2][4];
            #pragma unroll
            for (int mi = 0; mi < 2; mi++) {
                int row = warp_m * 32 + mi * 16 + (lane & 15);
                int col = ki * 16 + (lane >> 4) * 8;
                uint32_t ad = sbase + (uint32_t)(row * LDA + col) * 2;
                ldsm4(a_h[mi], ad);
                ldsm4(a_l[mi], ad + PLANE_B);
            }
            #pragma unroll
            for (int ng = 0; ng < 4; ng++) {
                int nrow = warp_n * 64 + ng * 16 + (lane & 7) + ((lane >> 4) & 1) * 8;
                int ncol = ki * 16 + ((lane >> 3) & 1) * 8;
                uint32_t bd = sbase + 2 * PLANE_B + (uint32_t)(nrow * LDA + ncol) * 2;
                uint32_t bh[4], bl[4];
                ldsm4(bh, bd);
                ldsm4(bl, bd + PLANE_B);
                #pragma unroll
                for (int mi = 0; mi < 2; mi++) {
                    mma_bf(acc[mi][2 * ng],     a_h[mi], bh);
                    mma_bf(acc[mi][2 * ng],     a_h[mi], bl);
                    mma_bf(acc[mi][2 * ng],     a_l[mi], bh);
                    mma_bf(acc[mi][2 * ng + 1], a_h[mi], bh + 2);
                    mma_bf(acc[mi][2 * ng + 1], a_h[mi], bl + 2);
                    mma_bf(acc[mi][2 * ng + 1], a_l[mi], bh + 2);
                }
            }
        }
    }

    __syncthreads();   // all compute done; smem reusable for staging

    int gID = lane >> 2, t4 = lane & 3;

    if (MODE == 3) {
        // stage transposed: Ts[o][n], stride 132
        #pragma unroll
        for (int mi = 0; mi < 2; mi++)
            #pragma unroll
            for (int ni = 0; ni < 8; ni++) {
                int r0 = warp_m * 32 + mi * 16 + gID;
                int c  = warp_n * 64 + ni * 8 + t4 * 2;
                Ts[c * 132 + r0]           = acc[mi][ni][0];
                Ts[(c + 1) * 132 + r0]     = acc[mi][ni][1];
                Ts[c * 132 + r0 + 8]       = acc[mi][ni][2];
                Ts[(c + 1) * 132 + r0 + 8] = acc[mi][ni][3];
            }
        __syncthreads();
        int b = n0 >> 12, hw0 = n0 & 4095;
        float* ybase = g_yraw + (size_t)b * (256 * 4096) + hw0;
        #pragma unroll
        for (int p = 0; p < 16; p++) {
            int q = p * 256 + tid;          // 0..4095
            int o = q >> 5, seg = q & 31;
            float4 v = *(float4*)&Ts[o * 132 + seg * 4];
            *(float4*)(ybase + (size_t)(m0 + o) * 4096 + seg * 4) = v;
        }
        return;
    }

    // MODE 1 / 2: stage row-major Ts[n][c], stride 132 (exp applied for MODE 1)
    #pragma unroll
    for (int mi = 0; mi < 2; mi++)
        #pragma unroll
        for (int ni = 0; ni < 8; ni++) {
            int r0 = warp_m * 32 + mi * 16 + gID;
            int c  = warp_n * 64 + ni * 8 + t4 * 2;
            if (MODE == 1) {
                Ts[r0 * 132 + c]           = expf(acc[mi][ni][0]);
                Ts[r0 * 132 + c + 1]       = expf(acc[mi][ni][1]);
                Ts[(r0 + 8) * 132 + c]     = expf(acc[mi][ni][2]);
                Ts[(r0 + 8) * 132 + c + 1] = expf(acc[mi][ni][3]);
            } else {
                Ts[r0 * 132 + c]           = acc[mi][ni][0];
                Ts[r0 * 132 + c + 1]       = acc[mi][ni][1];
                Ts[(r0 + 8) * 132 + c]     = acc[mi][ni][2];
                Ts[(r0 + 8) * 132 + c + 1] = acc[mi][ni][3];
            }
        }
    __syncthreads();

    if (MODE == 1) {
        // deterministic row partial sums over this 128-col tile
        int r = tid >> 1, half = tid & 1;
        float s = 0.f;
        #pragma unroll 16
        for (int j = 0; j < 64; j++) s += Ts[r * 132 + half * 64 + j];
        red[tid] = s;
        __syncthreads();
        if (tid < 128) g_rowpart[blockIdx.x][n0 + tid] = red[2 * tid] + red[2 * tid + 1];
    }

    // pack bf16 hi/lo, fully coalesced
    #pragma unroll
    for (int p = 0; p < 8; p++) {
        int cid = p * 256 + tid;            // 0..2047
        int r = cid >> 4, cc = cid & 15;
        float rv = 1.f;
        if (MODE == 2) rv = g_rinv[n0 + r];
        uint32_t hp[4], lp[4];
        #pragma unroll
        for (int jj = 0; jj < 4; jj++) {
            float v0 = Ts[r * 132 + cc * 8 + 2 * jj];
            float v1 = Ts[r * 132 + cc * 8 + 2 * jj + 1];
            if (MODE == 2) { v0 *= rv; v1 *= rv; }
            __nv_bfloat16 h0, l0, h1, l1;
            split_bf(v0, h0, l0);
            split_bf(v1, h1, l1);
            hp[jj] = pack_bf2(h0, h1);
            lp[jj] = pack_bf2(l0, l1);
        }
        if (MODE == 1) {
            size_t off = (size_t)(n0 + r) * 512 + m0 + cc * 8;
            *(uint4*)(g_E_hi + off) = *(uint4*)hp;
            *(uint4*)(g_E_lo + off) = *(uint4*)lp;
        } else {
            size_t off = (size_t)(n0 + r) * 256 + m0 + cc * 8;
            *(uint4*)(g_cm_hi + off) = *(uint4*)hp;
            *(uint4*)(g_cm_lo + off) = *(uint4*)lp;
        }
    }
}

// ---------------- rinv from row partials ----------------
__global__ void k_rinv() {
    int n = blockIdx.x * 256 + threadIdx.x;
    g_rinv[n] = 1.0f / (g_rowpart[0][n] + g_rowpart[1][n] + g_rowpart[2][n] + g_rowpart[3][n]);
}

// ---------------- column partial sums of E (deterministic) ----------------
__global__ void k_colpart() {
    int m = threadIdx.x;          // 512 threads
    int bi = blockIdx.x;          // 256 blocks x 256 rows
    const __nv_bfloat16* ph = g_E_hi + (size_t)bi * 256 * 512 + m;
    const __nv_bfloat16* pl = g_E_lo + (size_t)bi * 256 * 512 + m;
    float s = 0.f;
    #pragma unroll 8
    for (int r = 0; r < 256; r++)
        s += __bfloat162float(ph[(size_t)r * 512]) + __bfloat162float(pl[(size_t)r * 512]);
    g_colpart[bi * 512 + m] = s;
}

__global__ void k_colfin() {
    int m = threadIdx.x;
    float s = 0.f;
    #pragma unroll 8
    for (int b = 0; b < 256; b++) s += g_colpart[b * 512 + m];
    g_cinv[m] = 1.0f / s;
}

// ---------------- write both softmax outputs ----------------
__global__ void k_soft(float* __restrict__ ssq, float* __restrict__ ssm) {
    size_t idx = (size_t)blockIdx.x * 256 + threadIdx.x;
    size_t e0 = idx * 8;
    int n = (int)(e0 >> 9);
    int m = (int)(e0 & 511);
    uint4 hv = *(const uint4*)(g_E_hi + e0);
    uint4 lv = *(const uint4*)(g_E_lo + e0);
    float rv = g_rinv[n];
    const __nv_bfloat162* hp = (const __nv_bfloat162*)&hv;
    const __nv_bfloat162* lp = (const __nv_bfloat162*)&lv;
    float eo[8];
    #pragma unroll
    for (int i = 0; i < 4; i++) {
        float2 h2 = __bfloat1622float2(hp[i]);
        float2 l2 = __bfloat1622float2(lp[i]);
        eo[2 * i]     = h2.x + l2.x;
        eo[2 * i + 1] = h2.y + l2.y;
    }
    float4 sm0 = make_float4(eo[0] * rv, eo[1] * rv, eo[2] * rv, eo[3] * rv);
    float4 sm1 = make_float4(eo[4] * rv, eo[5] * rv, eo[6] * rv, eo[7] * rv);
    float4 sq0 = make_float4(eo[0] * g_cinv[m], eo[1] * g_cinv[m + 1],
                             eo[2] * g_cinv[m + 2], eo[3] * g_cinv[m + 3]);
    float4 sq1 = make_float4(eo[4] * g_cinv[m + 4], eo[5] * g_cinv[m + 5],
                             eo[6] * g_cinv[m + 6], eo[7] * g_cinv[m + 7]);
    *(float4*)(ssm + e0) = sm0;
    *(float4*)(ssm + e0 + 4) = sm1;
    *(float4*)(ssq + e0) = sq0;
    *(float4*)(ssq + e0 + 4) = sq1;
}

// ---------------- BN statistics (deterministic) ----------------
__global__ void k_stats() {
    int o = blockIdx.x;
    __shared__ float ssum[256];
    __shared__ float ssq2[256];
    float s = 0.f, q2 = 0.f;
    for (int t = threadIdx.x; t < 65536; t += 256) {
        int b = t >> 12, hw = t & 4095;
        float v = g_yraw[(size_t)b * (256 * 4096) + (size_t)o * 4096 + hw];
        s += v; q2 += v * v;
    }
    ssum[threadIdx.x] = s; ssq2[threadIdx.x] = q2;
    __syncthreads();
    for (int off = 128; off; off >>= 1) {
        if (threadIdx.x < off) {
            ssum[threadIdx.x] += ssum[threadIdx.x + off];
            ssq2[threadIdx.x] += ssq2[threadIdx.x + off];
        }
        __syncthreads();
    }
    if (threadIdx.x == 0) {
        float mean = ssum[0] * (1.0f / 65536.0f);
        float var  = ssq2[0] * (1.0f / 65536.0f) - mean * mean;
        g_mean[o] = mean;
        g_rstd[o] = rsqrtf(var + 1e-5f);
    }
}

// ---------------- BN affine + ReLU ----------------
__global__ void k_bn(const float* __restrict__ gamma, const float* __restrict__ beta,
                     float* __restrict__ yout) {
    int idx = blockIdx.x * blockDim.x + threadIdx.x;
    size_t e0 = (size_t)idx * 4;
    int o = (int)((e0 >> 12) & 255);
    float4 v = *(const float4*)(g_yraw + e0);
    float sc = g_rstd[o] * gamma[o];
    float sh = beta[o] - g_mean[o] * sc;
    float4 r = make_float4(fmaxf(v.x * sc + sh, 0.f), fmaxf(v.y * sc + sh, 0.f),
                           fmaxf(v.z * sc + sh, 0.f), fmaxf(v.w * sc + sh, 0.f));
    *(float4*)(yout + e0) = r;
}

// ---------------- launch ----------------
extern "C" void kernel_launch(void* const* d_in, const int* in_sizes, int n_in,
                              void* d_out, int out_size) {
    const float* query = (const float*)d_in[0];
    const float* mem   = (const float*)d_in[1];
    const float* convw = (const float*)d_in[2];
    const float* gamma = (const float*)d_in[3];
    const float* beta  = (const float*)d_in[4];

    float* out = (float*)d_out;
    float* y_out   = out;
    float* ssq_out = out + 16777216;
    float* ssm_out = out + 16777216 + 33554432;

    cudaFuncSetAttribute(k_gemm_mma<1>, cudaFuncAttributeMaxDynamicSharedMemorySize, SMEM_DYN);
    cudaFuncSetAttribute(k_gemm_mma<2>, cudaFuncAttributeMaxDynamicSharedMemorySize, SMEM_DYN);
    cudaFuncSetAttribute(k_gemm_mma<3>, cudaFuncAttributeMaxDynamicSharedMemorySize, SMEM_DYN);

    k_norm   <<<2048, 256>>>(query);
    k_prep   <<<512, 256>>>(mem, convw);
    k_gemm_mma<1><<<dim3(4, 512), 256, SMEM_DYN>>>();
    k_rinv   <<<256, 256>>>();
    k_colpart<<<256, 512>>>();
    k_colfin <<<1, 512>>>();
    k_soft   <<<16384, 256>>>(ssq_out, ssm_out);
    k_gemm_mma<2><<<dim3(2, 512), 256, SMEM_DYN>>>();
    k_gemm_mma<3><<<dim3(2, 512), 256, SMEM_DYN>>>();
    k_stats  <<<256, 256>>>();
    k_bn     <<<16384, 256>>>(gamma, beta, y_out);
}

// round 5
// speedup vs baseline: 2.1951x; 1.0806x over previous
#include <cuda_runtime.h>
#include <cuda_bf16.h>
#include <math.h>
#include <stdint.h>

// Problem constants: B=16, C=256, H=W=64, M=512
#define NROWS 65536
#define CDIM  256
#define MDIM  512
#define HWDIM 4096

// ---------------- scratch (device globals; no allocation) ----------------
__device__ __nv_bfloat16 g_qn_hi[NROWS * CDIM];
__device__ __nv_bfloat16 g_qn_lo[NROWS * CDIM];
__device__ __nv_bfloat16 g_E_hi[(size_t)NROWS * MDIM];
__device__ __nv_bfloat16 g_E_lo[(size_t)NROWS * MDIM];
__device__ __nv_bfloat16 g_mem_hi[MDIM * CDIM];
__device__ __nv_bfloat16 g_mem_lo[MDIM * CDIM];
__device__ __nv_bfloat16 g_w1_hi[CDIM * CDIM];     // conv_w[:, 0:256] as [o][k]
__device__ __nv_bfloat16 g_w1_lo[CDIM * CDIM];
__device__ __nv_bfloat16 g_p_hi[CDIM * MDIM];      // P^T[o][m] = sum_c mem[m,c]*W2[o,c]
__device__ __nv_bfloat16 g_p_lo[CDIM * MDIM];
__device__ float g_mTf[CDIM * MDIM];               // mem transposed fp32 [c][m]
__device__ float g_yraw[NROWS * CDIM];
__device__ float g_rowpart[4][NROWS];
__device__ float g_rinv[NROWS];
__device__ float g_cp[512 * MDIM];                 // col-sum partials per n-block
__device__ float g_cinv[MDIM];
__device__ float g_sp[512 * CDIM];                 // BN sum partials per n-block
__device__ float g_sp2[512 * CDIM];                // BN sumsq partials
__device__ float g_mean[256];
__device__ float g_rstd[256];

// ---------------- helpers ----------------
__device__ __forceinline__ uint32_t s2u(const void* p) {
    uint32_t a;
    asm("{ .reg .u64 t; cvta.to.shared.u64 t, %1; cvt.u32.u64 %0, t; }" : "=r"(a) : "l"(p));
    return a;
}
__device__ __forceinline__ void cp16(uint32_t s, const void* g) {
    asm volatile("cp.async.ca.shared.global [%0], [%1], 16;" :: "r"(s), "l"(g));
}
__device__ __forceinline__ void ldsm4(uint32_t* r, uint32_t addr) {
    asm volatile("ldmatrix.sync.aligned.m8n8.x4.shared.b16 {%0,%1,%2,%3}, [%4];"
                 : "=r"(r[0]), "=r"(r[1]), "=r"(r[2]), "=r"(r[3]) : "r"(addr));
}
__device__ __forceinline__ void mma_bf(float* d, const uint32_t* a, const uint32_t* b) {
    asm volatile(
        "mma.sync.aligned.m16n8k16.row.col.f32.bf16.bf16.f32 "
        "{%0,%1,%2,%3}, {%4,%5,%6,%7}, {%8,%9}, {%0,%1,%2,%3};"
        : "+f"(d[0]), "+f"(d[1]), "+f"(d[2]), "+f"(d[3])
        : "r"(a[0]), "r"(a[1]), "r"(a[2]), "r"(a[3]), "r"(b[0]), "r"(b[1]));
}
__device__ __forceinline__ uint32_t pack_bf2(__nv_bfloat16 a, __nv_bfloat16 b) {
    return ((uint32_t)__bfloat16_as_ushort(b) << 16) | (uint32_t)__bfloat16_as_ushort(a);
}
__device__ __forceinline__ void split_bf(float v, __nv_bfloat16& h, __nv_bfloat16& l) {
    h = __float2bfloat16(v);
    l = __float2bfloat16(v - __bfloat162float(h));
}

// ---------------- K1: channel-normalize + transpose, write bf16 hi/lo ----------------
__global__ void k_norm(const float* __restrict__ q) {
    __shared__ float s[256][33];
    __shared__ float red[8][32];
    __shared__ float invs[32];
    int n0 = blockIdx.x * 32;
    int b  = n0 >> 12;
    int hw0 = n0 & 4095;
    const float* base = q + (size_t)b * CDIM * HWDIM + hw0;
    for (int idx = threadIdx.x; idx < 256 * 32; idx += 256) {
        int c = idx >> 5, j = idx & 31;
        s[c][j] = base[c * HWDIM + j];
    }
    __syncthreads();
    int j = threadIdx.x & 31, g = threadIdx.x >> 5;
    float p = 0.f;
    #pragma unroll 8
    for (int c = g; c < 256; c += 8) { float v = s[c][j]; p += v * v; }
    red[g][j] = p;
    __syncthreads();
    if (threadIdx.x < 32) {
        float t = 0.f;
        #pragma unroll
        for (int gg = 0; gg < 8; gg++) t += red[gg][threadIdx.x];
        invs[threadIdx.x] = 1.0f / fmaxf(sqrtf(t), 1e-12f);
    }
    __syncthreads();
    for (int idx = threadIdx.x; idx < 256 * 32; idx += 256) {
        int jj = idx >> 8, c = idx & 255;
        float v = s[c][jj] * invs[jj];
        __nv_bfloat16 h, l; split_bf(v, h, l);
        size_t off = (size_t)(n0 + jj) * 256 + c;
        g_qn_hi[off] = h;
        g_qn_lo[off] = l;
    }
}

// ---------------- prep: mem split + fp32 transpose; W1 split ----------------
__global__ void k_prep(const float* __restrict__ mem, const float* __restrict__ w) {
    int i = blockIdx.x * 256 + threadIdx.x;   // 131072
    float v = mem[i];
    __nv_bfloat16 h, l; split_bf(v, h, l);
    g_mem_hi[i] = h; g_mem_lo[i] = l;
    int m = i >> 8, c = i & 255;
    g_mTf[c * 512 + m] = v;
    float wv = w[i];
    int o = i >> 9, k = i & 511;
    if (k < 256) {
        __nv_bfloat16 wh, wl; split_bf(wv, wh, wl);
        g_w1_hi[o * 256 + k] = wh;
        g_w1_lo[o * 256 + k] = wl;
    }
}

// ---------------- P^T[o][m] = sum_c mem[m,c] * conv_w[o, 256+c] (fp32) ----------------
__global__ void k_compP(const float* __restrict__ w) {
    __shared__ float sw[8][256];
    int m = blockIdx.x * 256 + threadIdx.x;   // grid.x = 2
    int o0 = blockIdx.y * 8;                  // grid.y = 32
    for (int idx = threadIdx.x; idx < 8 * 256; idx += 256) {
        int jj = idx >> 8, c = idx & 255;
        sw[jj][c] = w[(size_t)(o0 + jj) * 512 + 256 + c];
    }
    __syncthreads();
    float acc[8] = {};
    for (int c = 0; c < 256; c++) {
        float v = g_mTf[c * 512 + m];
        #pragma unroll
        for (int jj = 0; jj < 8; jj++) acc[jj] += v * sw[jj][c];
    }
    #pragma unroll
    for (int jj = 0; jj < 8; jj++) {
        __nv_bfloat16 h, l; split_bf(acc[jj], h, l);
        g_p_hi[(o0 + jj) * 512 + m] = h;
        g_p_lo[(o0 + jj) * 512 + m] = l;
    }
}

// ---------------- mma.sync bf16x3 GEMM ----------------
// MODE 1: E = exp(qn @ mem^T)  [N,512], K=256, grid(4,512); fused row+col partials
// MODE 2: y = rinv*(E @ P^T) + qn @ W1^T, K=512+256, grid(2,512); BOHW store + BN partials
#define LDA 40                       // halves per smem row (32 + 8 pad)
#define PLANE_B (128 * LDA * 2)      // 10240 bytes per plane
#define STAGE_B (4 * PLANE_B)        // Ah, Al, Bh, Bl = 40960
#define SMEM_DYN (2 * STAGE_B)       // 81920

template <int MODE>
__global__ __launch_bounds__(256, 1) void k_gemm_mma() {
    extern __shared__ __align__(16) char smem_raw[];
    uint32_t smem_u = s2u(smem_raw);
    float* Ts   = (float*)smem_raw;               // epilogue staging 128x132
    float* red1 = (float*)smem_raw + 16896;       // 256 floats
    float* red2 = (float*)smem_raw + 17152;       // 256 floats

    int tid = threadIdx.x, lane = tid & 31, wid = tid >> 5;
    int warp_m = wid & 3, warp_n = wid >> 2;      // 4 x 2 warps, warp tile 32x64
    int n0 = blockIdx.y * 128;
    int m0 = blockIdx.x * 128;                    // m-block (MODE1) or o-block (MODE2)
    const int NITER = (MODE == 1) ? 8 : 24;
    int gID = lane >> 2, t4 = lane & 3;

    float acc[2][8][4];
    #pragma unroll
    for (int a = 0; a < 2; a++)
        #pragma unroll
        for (int b = 0; b < 8; b++)
            #pragma unroll
            for (int c = 0; c < 4; c++) acc[a][b][c] = 0.f;

    auto issue = [&](int kc) {
        const __nv_bfloat16 *Ah, *Al, *Bh, *Bl;
        int aS, bS, ak0, bk0;
        if (MODE == 1) {
            Ah = g_qn_hi; Al = g_qn_lo; aS = 256; ak0 = kc * 32;
            Bh = g_mem_hi; Bl = g_mem_lo; bS = 256; bk0 = kc * 32;
        } else if (kc < 16) {
            Ah = g_E_hi; Al = g_E_lo; aS = 512; ak0 = kc * 32;
            Bh = g_p_hi; Bl = g_p_lo; bS = 512; bk0 = kc * 32;
        } else {
            Ah = g_qn_hi; Al = g_qn_lo; aS = 256; ak0 = (kc - 16) * 32;
            Bh = g_w1_hi; Bl = g_w1_lo; bS = 256; bk0 = (kc - 16) * 32;
        }
        uint32_t sb = smem_u + (kc & 1) * STAGE_B;
        #pragma unroll
        for (int it = 0; it < 2; it++) {
            int i = tid + it * 256;
            int r = i >> 2, seg = i & 3;
            uint32_t so = sb + (uint32_t)(r * LDA + seg * 8) * 2;
            size_t aoff = (size_t)(n0 + r) * aS + ak0 + seg * 8;
            size_t boff = (size_t)(m0 + r) * bS + bk0 + seg * 8;
            cp16(so,               Ah + aoff);
            cp16(so + PLANE_B,     Al + aoff);
            cp16(so + 2 * PLANE_B, Bh + boff);
            cp16(so + 3 * PLANE_B, Bl + boff);
        }
        asm volatile("cp.async.commit_group;" ::: "memory");
    };

    issue(0);
    for (int kc = 0; kc < NITER; kc++) {
        __syncthreads();
        if (kc + 1 < NITER) {
            issue(kc + 1);
            asm volatile("cp.async.wait_group 1;" ::: "memory");
        } else {
            asm volatile("cp.async.wait_group 0;" ::: "memory");
        }
        __syncthreads();

        uint32_t sbase = smem_u + (kc & 1) * STAGE_B;
        #pragma unroll
        for (int ki = 0; ki < 2; ki++) {
            uint32_t a_h[2][4], a_l[2][4];
            #pragma unroll
            for (int mi = 0; mi < 2; mi++) {
                int row = warp_m * 32 + mi * 16 + (lane & 15);
                int col = ki * 16 + (lane >> 4) * 8;
                uint32_t ad = sbase + (uint32_t)(row * LDA + col) * 2;
                ldsm4(a_h[mi], ad);
                ldsm4(a_l[mi], ad + PLANE_B);
            }
            #pragma unroll
            for (int ng = 0; ng < 4; ng++) {
                int nrow = warp_n * 64 + ng * 16 + (lane & 7) + ((lane >> 4) & 1) * 8;
                int ncol = ki * 16 + ((lane >> 3) & 1) * 8;
                uint32_t bd = sbase + 2 * PLANE_B + (uint32_t)(nrow * LDA + ncol) * 2;
                uint32_t bh[4], bl[4];
                ldsm4(bh, bd);
                ldsm4(bl, bd + PLANE_B);
                #pragma unroll
                for (int mi = 0; mi < 2; mi++) {
                    mma_bf(acc[mi][2 * ng],     a_h[mi], bh);
                    mma_bf(acc[mi][2 * ng],     a_h[mi], bl);
                    mma_bf(acc[mi][2 * ng],     a_l[mi], bh);
                    mma_bf(acc[mi][2 * ng + 1], a_h[mi], bh + 2);
                    mma_bf(acc[mi][2 * ng + 1], a_h[mi], bl + 2);
                    mma_bf(acc[mi][2 * ng + 1], a_l[mi], bh + 2);
                }
            }
        }

        if (MODE == 2 && kc == 15) {
            // scale phase-1 accumulator (E @ P^T) by rinv per output row
            #pragma unroll
            for (int mi = 0; mi < 2; mi++) {
                float rv0 = g_rinv[n0 + warp_m * 32 + mi * 16 + gID];
                float rv1 = g_rinv[n0 + warp_m * 32 + mi * 16 + gID + 8];
                #pragma unroll
                for (int ni = 0; ni < 8; ni++) {
                    acc[mi][ni][0] *= rv0;
                    acc[mi][ni][1] *= rv0;
                    acc[mi][ni][2] *= rv1;
                    acc[mi][ni][3] *= rv1;
                }
            }
        }
    }

    __syncthreads();   // all compute done; smem reusable for staging

    if (MODE == 2) {
        // stage transposed: Ts[o][n], stride 132
        #pragma unroll
        for (int mi = 0; mi < 2; mi++)
            #pragma unroll
            for (int ni = 0; ni < 8; ni++) {
                int r0 = warp_m * 32 + mi * 16 + gID;
                int c  = warp_n * 64 + ni * 8 + t4 * 2;
                Ts[c * 132 + r0]           = acc[mi][ni][0];
                Ts[(c + 1) * 132 + r0]     = acc[mi][ni][1];
                Ts[c * 132 + r0 + 8]       = acc[mi][ni][2];
                Ts[(c + 1) * 132 + r0 + 8] = acc[mi][ni][3];
            }
        __syncthreads();
        int b = n0 >> 12, hw0 = n0 & 4095;
        float* ybase = g_yraw + (size_t)b * (256 * 4096) + hw0;
        #pragma unroll
        for (int p = 0; p < 16; p++) {
            int q = p * 256 + tid;
            int o = q >> 5, seg = q & 31;
            float4 v = *(float4*)&Ts[o * 132 + seg * 4];
            *(float4*)(ybase + (size_t)(m0 + o) * 4096 + seg * 4) = v;
        }
        // BN partial sums per o over this block's 128 rows
        {
            int o = tid >> 1, half = tid & 1;
            float s = 0.f, s2 = 0.f;
            #pragma unroll 16
            for (int jj = 0; jj < 64; jj++) {
                float v = Ts[o * 132 + half * 64 + jj];
                s += v; s2 += v * v;
            }
            red1[tid] = s; red2[tid] = s2;
        }
        __syncthreads();
        if (tid < 128) {
            g_sp [blockIdx.y * 256 + m0 + tid] = red1[2 * tid] + red1[2 * tid + 1];
            g_sp2[blockIdx.y * 256 + m0 + tid] = red2[2 * tid] + red2[2 * tid + 1];
        }
        return;
    }

    // MODE 1: stage exp values row-major Ts[n][c], stride 132
    #pragma unroll
    for (int mi = 0; mi < 2; mi++)
        #pragma unroll
        for (int ni = 0; ni < 8; ni++) {
            int r0 = warp_m * 32 + mi * 16 + gID;
            int c  = warp_n * 64 + ni * 8 + t4 * 2;
            Ts[r0 * 132 + c]           = expf(acc[mi][ni][0]);
            Ts[r0 * 132 + c + 1]       = expf(acc[mi][ni][1]);
            Ts[(r0 + 8) * 132 + c]     = expf(acc[mi][ni][2]);
            Ts[(r0 + 8) * 132 + c + 1] = expf(acc[mi][ni][3]);
        }
    __syncthreads();

    // deterministic row partial sums over this 128-col tile
    {
        int r = tid >> 1, half = tid & 1;
        float s = 0.f;
        #pragma unroll 16
        for (int jj = 0; jj < 64; jj++) s += Ts[r * 132 + half * 64 + jj];
        red1[tid] = s;
    }
    // deterministic column partial sums over this block's 128 rows
    {
        int c = tid & 127, half = tid >> 7;
        float s = 0.f;
        #pragma unroll 16
        for (int rr = 0; rr < 64; rr++) s += Ts[(half * 64 + rr) * 132 + c];
        red2[tid] = s;
    }
    __syncthreads();
    if (tid < 128) {
        g_rowpart[blockIdx.x][n0 + tid] = red1[2 * tid] + red1[2 * tid + 1];
        g_cp[blockIdx.y * 512 + m0 + tid] = red2[tid] + red2[tid + 128];
    }

    // pack bf16 hi/lo, fully coalesced
    #pragma unroll
    for (int p = 0; p < 8; p++) {
        int cid = p * 256 + tid;
        int r = cid >> 4, cc = cid & 15;
        uint32_t hp[4], lp[4];
        #pragma unroll
        for (int jj = 0; jj < 4; jj++) {
            float v0 = Ts[r * 132 + cc * 8 + 2 * jj];
            float v1 = Ts[r * 132 + cc * 8 + 2 * jj + 1];
            __nv_bfloat16 h0, l0, h1, l1;
            split_bf(v0, h0, l0);
            split_bf(v1, h1, l1);
            hp[jj] = pack_bf2(h0, h1);
            lp[jj] = pack_bf2(l0, l1);
        }
        size_t off = (size_t)(n0 + r) * 512 + m0 + cc * 8;
        *(uint4*)(g_E_hi + off) = *(uint4*)hp;
        *(uint4*)(g_E_lo + off) = *(uint4*)lp;
    }
}

// ---------------- rinv from row partials ----------------
__global__ void k_rinv() {
    int n = blockIdx.x * 256 + threadIdx.x;
    g_rinv[n] = 1.0f / (g_rowpart[0][n] + g_rowpart[1][n] + g_rowpart[2][n] + g_rowpart[3][n]);
}

// ---------------- cinv from column partials ----------------
__global__ void k_colfin() {
    int m = threadIdx.x;   // 512 threads, 1 block
    float s = 0.f;
    #pragma unroll 8
    for (int y = 0; y < 512; y++) s += g_cp[y * 512 + m];
    g_cinv[m] = 1.0f / s;
}

// ---------------- write both softmax outputs ----------------
__global__ void k_soft(float* __restrict__ ssq, float* __restrict__ ssm) {
    size_t idx = (size_t)blockIdx.x * 256 + threadIdx.x;
    size_t e0 = idx * 8;
    int n = (int)(e0 >> 9);
    int m = (int)(e0 & 511);
    uint4 hv = *(const uint4*)(g_E_hi + e0);
    uint4 lv = *(const uint4*)(g_E_lo + e0);
    float rv = g_rinv[n];
    const __nv_bfloat162* hp = (const __nv_bfloat162*)&hv;
    const __nv_bfloat162* lp = (const __nv_bfloat162*)&lv;
    float eo[8];
    #pragma unroll
    for (int i = 0; i < 4; i++) {
        float2 h2 = __bfloat1622float2(hp[i]);
        float2 l2 = __bfloat1622float2(lp[i]);
        eo[2 * i]     = h2.x + l2.x;
        eo[2 * i + 1] = h2.y + l2.y;
    }
    float4 sm0 = make_float4(eo[0] * rv, eo[1] * rv, eo[2] * rv, eo[3] * rv);
    float4 sm1 = make_float4(eo[4] * rv, eo[5] * rv, eo[6] * rv, eo[7] * rv);
    float4 sq0 = make_float4(eo[0] * g_cinv[m], eo[1] * g_cinv[m + 1],
                             eo[2] * g_cinv[m + 2], eo[3] * g_cinv[m + 3]);
    float4 sq1 = make_float4(eo[4] * g_cinv[m + 4], eo[5] * g_cinv[m + 5],
                             eo[6] * g_cinv[m + 6], eo[7] * g_cinv[m + 7]);
    *(float4*)(ssm + e0) = sm0;
    *(float4*)(ssm + e0 + 4) = sm1;
    *(float4*)(ssq + e0) = sq0;
    *(float4*)(ssq + e0 + 4) = sq1;
}

// ---------------- BN statistics finalize from partials ----------------
__global__ void k_statfin() {
    int o = threadIdx.x;   // 256 threads, 1 block
    float s = 0.f, s2 = 0.f;
    #pragma unroll 8
    for (int y = 0; y < 512; y++) {
        s  += g_sp [y * 256 + o];
        s2 += g_sp2[y * 256 + o];
    }
    float mean = s * (1.0f / 65536.0f);
    float var  = s2 * (1.0f / 65536.0f) - mean * mean;
    g_mean[o] = mean;
    g_rstd[o] = rsqrtf(var + 1e-5f);
}

// ---------------- BN affine + ReLU ----------------
__global__ void k_bn(const float* __restrict__ gamma, const float* __restrict__ beta,
                     float* __restrict__ yout) {
    int idx = blockIdx.x * blockDim.x + threadIdx.x;
    size_t e0 = (size_t)idx * 4;
    int o = (int)((e0 >> 12) & 255);
    float4 v = *(const float4*)(g_yraw + e0);
    float sc = g_rstd[o] * gamma[o];
    float sh = beta[o] - g_mean[o] * sc;
    float4 r = make_float4(fmaxf(v.x * sc + sh, 0.f), fmaxf(v.y * sc + sh, 0.f),
                           fmaxf(v.z * sc + sh, 0.f), fmaxf(v.w * sc + sh, 0.f));
    *(float4*)(yout + e0) = r;
}

// ---------------- launch ----------------
extern "C" void kernel_launch(void* const* d_in, const int* in_sizes, int n_in,
                              void* d_out, int out_size) {
    const float* query = (const float*)d_in[0];
    const float* mem   = (const float*)d_in[1];
    const float* convw = (const float*)d_in[2];
    const float* gamma = (const float*)d_in[3];
    const float* beta  = (const float*)d_in[4];

    float* out = (float*)d_out;
    float* y_out   = out;
    float* ssq_out = out + 16777216;
    float* ssm_out = out + 16777216 + 33554432;

    cudaFuncSetAttribute(k_gemm_mma<1>, cudaFuncAttributeMaxDynamicSharedMemorySize, SMEM_DYN);
    cudaFuncSetAttribute(k_gemm_mma<2>, cudaFuncAttributeMaxDynamicSharedMemorySize, SMEM_DYN);

    k_norm   <<<2048, 256>>>(query);
    k_prep   <<<512, 256>>>(mem, convw);
    k_compP  <<<dim3(2, 32), 256>>>(convw);
    k_gemm_mma<1><<<dim3(4, 512), 256, SMEM_DYN>>>();
    k_rinv   <<<256, 256>>>();
    k_colfin <<<1, 512>>>();
    k_soft   <<<16384, 256>>>(ssq_out, ssm_out);
    k_gemm_mma<2><<<dim3(2, 512), 256, SMEM_DYN>>>();
    k_statfin<<<1, 256>>>();
    k_bn     <<<16384, 256>>>(gamma, beta, y_out);
}

// round 6
// speedup vs baseline: 2.2821x; 1.0397x over previous
#include <cuda_runtime.h>
#include <cuda_bf16.h>
#include <math.h>
#include <stdint.h>

// Problem constants: B=16, C=256, H=W=64, M=512
#define NROWS 65536
#define CDIM  256
#define MDIM  512
#define HWDIM 4096

// ---------------- scratch (device globals; no allocation) ----------------
__device__ __nv_bfloat16 g_qn_hi[NROWS * CDIM];
__device__ __nv_bfloat16 g_qn_lo[NROWS * CDIM];
__device__ __nv_bfloat16 g_E_hi[(size_t)NROWS * MDIM];
__device__ __nv_bfloat16 g_E_lo[(size_t)NROWS * MDIM];
__device__ __nv_bfloat16 g_mem_hi[MDIM * CDIM];
__device__ __nv_bfloat16 g_mem_lo[MDIM * CDIM];
__device__ __nv_bfloat16 g_w1_hi[CDIM * CDIM];     // conv_w[:, 0:256] as [o][k]
__device__ __nv_bfloat16 g_w1_lo[CDIM * CDIM];
__device__ __nv_bfloat16 g_p_hi[CDIM * MDIM];      // P^T[o][m] = sum_c mem[m,c]*W2[o,c]
__device__ __nv_bfloat16 g_p_lo[CDIM * MDIM];
__device__ float g_mTf[CDIM * MDIM];               // mem transposed fp32 [c][m]
__device__ float g_yraw[NROWS * CDIM];
__device__ float g_rowpart[4][NROWS];
__device__ float g_rinv[NROWS];
__device__ float g_cp[256 * MDIM];                 // col-sum partials per n-block (256 blocks)
__device__ float g_cinv[MDIM];
__device__ float g_sp[256 * CDIM];                 // BN sum partials per n-block
__device__ float g_sp2[256 * CDIM];                // BN sumsq partials
__device__ float g_mean[256];
__device__ float g_rstd[256];

// ---------------- helpers ----------------
__device__ __forceinline__ uint32_t s2u(const void* p) {
    uint32_t a;
    asm("{ .reg .u64 t; cvta.to.shared.u64 t, %1; cvt.u32.u64 %0, t; }" : "=r"(a) : "l"(p));
    return a;
}
__device__ __forceinline__ void cp16(uint32_t s, const void* g) {
    asm volatile("cp.async.ca.shared.global [%0], [%1], 16;" :: "r"(s), "l"(g));
}
__device__ __forceinline__ void ldsm4(uint32_t* r, uint32_t addr) {
    asm volatile("ldmatrix.sync.aligned.m8n8.x4.shared.b16 {%0,%1,%2,%3}, [%4];"
                 : "=r"(r[0]), "=r"(r[1]), "=r"(r[2]), "=r"(r[3]) : "r"(addr));
}
__device__ __forceinline__ void mma_bf(float* d, const uint32_t* a, const uint32_t* b) {
    asm volatile(
        "mma.sync.aligned.m16n8k16.row.col.f32.bf16.bf16.f32 "
        "{%0,%1,%2,%3}, {%4,%5,%6,%7}, {%8,%9}, {%0,%1,%2,%3};"
        : "+f"(d[0]), "+f"(d[1]), "+f"(d[2]), "+f"(d[3])
        : "r"(a[0]), "r"(a[1]), "r"(a[2]), "r"(a[3]), "r"(b[0]), "r"(b[1]));
}
__device__ __forceinline__ uint32_t pack_bf2(__nv_bfloat16 a, __nv_bfloat16 b) {
    return ((uint32_t)__bfloat16_as_ushort(b) << 16) | (uint32_t)__bfloat16_as_ushort(a);
}
__device__ __forceinline__ void split_bf(float v, __nv_bfloat16& h, __nv_bfloat16& l) {
    h = __float2bfloat16(v);
    l = __float2bfloat16(v - __bfloat162float(h));
}

// ---------------- K1: channel-normalize + transpose, write bf16 hi/lo ----------------
__global__ void k_norm(const float* __restrict__ q) {
    __shared__ float s[256][33];
    __shared__ float red[8][32];
    __shared__ float invs[32];
    int n0 = blockIdx.x * 32;
    int b  = n0 >> 12;
    int hw0 = n0 & 4095;
    const float* base = q + (size_t)b * CDIM * HWDIM + hw0;
    for (int idx = threadIdx.x; idx < 256 * 32; idx += 256) {
        int c = idx >> 5, j = idx & 31;
        s[c][j] = base[c * HWDIM + j];
    }
    __syncthreads();
    int j = threadIdx.x & 31, g = threadIdx.x >> 5;
    float p = 0.f;
    #pragma unroll 8
    for (int c = g; c < 256; c += 8) { float v = s[c][j]; p += v * v; }
    red[g][j] = p;
    __syncthreads();
    if (threadIdx.x < 32) {
        float t = 0.f;
        #pragma unroll
        for (int gg = 0; gg < 8; gg++) t += red[gg][threadIdx.x];
        invs[threadIdx.x] = 1.0f / fmaxf(sqrtf(t), 1e-12f);
    }
    __syncthreads();
    for (int idx = threadIdx.x; idx < 256 * 32; idx += 256) {
        int jj = idx >> 8, c = idx & 255;
        float v = s[c][jj] * invs[jj];
        __nv_bfloat16 h, l; split_bf(v, h, l);
        size_t off = (size_t)(n0 + jj) * 256 + c;
        g_qn_hi[off] = h;
        g_qn_lo[off] = l;
    }
}

// ---------------- prep: mem split + fp32 transpose; W1 split ----------------
__global__ void k_prep(const float* __restrict__ mem, const float* __restrict__ w) {
    int i = blockIdx.x * 256 + threadIdx.x;   // 131072
    float v = mem[i];
    __nv_bfloat16 h, l; split_bf(v, h, l);
    g_mem_hi[i] = h; g_mem_lo[i] = l;
    int m = i >> 8, c = i & 255;
    g_mTf[c * 512 + m] = v;
    float wv = w[i];
    int o = i >> 9, k = i & 511;
    if (k < 256) {
        __nv_bfloat16 wh, wl; split_bf(wv, wh, wl);
        g_w1_hi[o * 256 + k] = wh;
        g_w1_lo[o * 256 + k] = wl;
    }
}

// ---------------- P^T[o][m] = sum_c mem[m,c] * conv_w[o, 256+c] (fp32) ----------------
__global__ void k_compP(const float* __restrict__ w) {
    __shared__ float sw[8][256];
    int m = blockIdx.x * 256 + threadIdx.x;   // grid.x = 2
    int o0 = blockIdx.y * 8;                  // grid.y = 32
    for (int idx = threadIdx.x; idx < 8 * 256; idx += 256) {
        int jj = idx >> 8, c = idx & 255;
        sw[jj][c] = w[(size_t)(o0 + jj) * 512 + 256 + c];
    }
    __syncthreads();
    float acc[8] = {};
    for (int c = 0; c < 256; c++) {
        float v = g_mTf[c * 512 + m];
        #pragma unroll
        for (int jj = 0; jj < 8; jj++) acc[jj] += v * sw[jj][c];
    }
    #pragma unroll
    for (int jj = 0; jj < 8; jj++) {
        __nv_bfloat16 h, l; split_bf(acc[jj], h, l);
        g_p_hi[(o0 + jj) * 512 + m] = h;
        g_p_lo[(o0 + jj) * 512 + m] = l;
    }
}

// ---------------- mma.sync bf16x3 GEMM, CTA tile 256x128, warp tile 64x64 ----------------
// MODE 1: E = exp(qn @ mem^T)  [N,512], K=256, grid(4,256); fused row+col partials
// MODE 2: y = rinv*(E @ P^T) + qn @ W1^T, K=512+256, grid(2,256); BOHW store + BN partials
#define LDA 40                        // halves per smem row (32 + 8 pad)
#define A_PLANE (256 * LDA * 2)       // 20480 bytes
#define B_PLANE (128 * LDA * 2)       // 10240 bytes
#define A_HI 0
#define A_LO A_PLANE
#define B_HI (2 * A_PLANE)
#define B_LO (2 * A_PLANE + B_PLANE)
#define STAGE_B (2 * A_PLANE + 2 * B_PLANE)   // 61440
#define NSTAGES 3
#define SMEM_DYN (NSTAGES * STAGE_B)          // 184320

template <int MODE>
__global__ __launch_bounds__(256, 1) void k_gemm_mma() {
    extern __shared__ __align__(16) char smem_raw[];
    uint32_t smem_u = s2u(smem_raw);
    float* Ts   = (float*)smem_raw;               // epilogue staging 128x132 (reuses stages)
    float* red1 = (float*)smem_raw + 16896;       // 256 floats @ 67584
    float* red2 = (float*)smem_raw + 17152;       // 256 floats

    int tid = threadIdx.x, lane = tid & 31, wid = tid >> 5;
    int warp_m = wid & 3, warp_n = wid >> 2;      // 4 x 2 warps, warp tile 64x64
    int n0 = blockIdx.y * 256;
    int m0 = blockIdx.x * 128;
    const int NITER = (MODE == 1) ? 8 : 24;
    int gID = lane >> 2, t4 = lane & 3;

    float acc[4][8][4];
    #pragma unroll
    for (int a = 0; a < 4; a++)
        #pragma unroll
        for (int b = 0; b < 8; b++)
            #pragma unroll
            for (int c = 0; c < 4; c++) acc[a][b][c] = 0.f;

    auto issue = [&](int kc) {
        const __nv_bfloat16 *Ah, *Al, *Bh, *Bl;
        int aS, bS, ak0, bk0;
        if (MODE == 1) {
            Ah = g_qn_hi; Al = g_qn_lo; aS = 256; ak0 = kc * 32;
            Bh = g_mem_hi; Bl = g_mem_lo; bS = 256; bk0 = kc * 32;
        } else if (kc < 16) {
            Ah = g_E_hi; Al = g_E_lo; aS = 512; ak0 = kc * 32;
            Bh = g_p_hi; Bl = g_p_lo; bS = 512; bk0 = kc * 32;
        } else {
            Ah = g_qn_hi; Al = g_qn_lo; aS = 256; ak0 = (kc - 16) * 32;
            Bh = g_w1_hi; Bl = g_w1_lo; bS = 256; bk0 = (kc - 16) * 32;
        }
        uint32_t sb = smem_u + (kc % NSTAGES) * STAGE_B;
        // A: 256 rows x 32 halves, hi + lo
        #pragma unroll
        for (int it = 0; it < 4; it++) {
            int i = tid + it * 256;
            int r = i >> 2, seg = i & 3;
            uint32_t so = sb + (uint32_t)(r * LDA + seg * 8) * 2;
            size_t aoff = (size_t)(n0 + r) * aS + ak0 + seg * 8;
            cp16(so + A_HI, Ah + aoff);
            cp16(so + A_LO, Al + aoff);
        }
        // B: 128 rows x 32 halves, hi + lo
        #pragma unroll
        for (int it = 0; it < 2; it++) {
            int i = tid + it * 256;
            int r = i >> 2, seg = i & 3;
            uint32_t so = sb + (uint32_t)(r * LDA + seg * 8) * 2;
            size_t boff = (size_t)(m0 + r) * bS + bk0 + seg * 8;
            cp16(so + B_HI, Bh + boff);
            cp16(so + B_LO, Bl + boff);
        }
        asm volatile("cp.async.commit_group;" ::: "memory");
    };

    issue(0);
    issue(1);
    for (int kc = 0; kc < NITER; kc++) {
        if (kc < NITER - 1) {
            asm volatile("cp.async.wait_group 1;" ::: "memory");
        } else {
            asm volatile("cp.async.wait_group 0;" ::: "memory");
        }
        __syncthreads();
        if (kc + 2 < NITER) issue(kc + 2);

        uint32_t sbase = smem_u + (kc % NSTAGES) * STAGE_B;
        #pragma unroll
        for (int ki = 0; ki < 2; ki++) {
            uint32_t b_h[4][4], b_l[4][4];
            #pragma unroll
            for (int ng = 0; ng < 4; ng++) {
                int nrow = warp_n * 64 + ng * 16 + (lane & 7) + ((lane >> 4) & 1) * 8;
                int ncol = ki * 16 + ((lane >> 3) & 1) * 8;
                uint32_t bd = sbase + B_HI + (uint32_t)(nrow * LDA + ncol) * 2;
                ldsm4(b_h[ng], bd);
                ldsm4(b_l[ng], bd + B_PLANE);
            }
            #pragma unroll
            for (int mi = 0; mi < 4; mi++) {
                int row = warp_m * 64 + mi * 16 + (lane & 15);
                int col = ki * 16 + (lane >> 4) * 8;
                uint32_t ad = sbase + A_HI + (uint32_t)(row * LDA + col) * 2;
                uint32_t a_h[4], a_l[4];
                ldsm4(a_h, ad);
                ldsm4(a_l, ad + A_PLANE);
                #pragma unroll
                for (int ng = 0; ng < 4; ng++) {
                    mma_bf(acc[mi][2 * ng],     a_h, b_h[ng]);
                    mma_bf(acc[mi][2 * ng],     a_h, b_l[ng]);
                    mma_bf(acc[mi][2 * ng],     a_l, b_h[ng]);
                    mma_bf(acc[mi][2 * ng + 1], a_h, b_h[ng] + 2);
                    mma_bf(acc[mi][2 * ng + 1], a_h, b_l[ng] + 2);
                    mma_bf(acc[mi][2 * ng + 1], a_l, b_h[ng] + 2);
                }
            }
        }

        if (MODE == 2 && kc == 15) {
            // scale phase-1 accumulator (E @ P^T) by rinv per output row
            #pragma unroll
            for (int mi = 0; mi < 4; mi++) {
                int r0 = n0 + warp_m * 64 + mi * 16 + gID;
                float rv0 = g_rinv[r0];
                float rv1 = g_rinv[r0 + 8];
                #pragma unroll
                for (int ni = 0; ni < 8; ni++) {
                    acc[mi][ni][0] *= rv0;
                    acc[mi][ni][1] *= rv0;
                    acc[mi][ni][2] *= rv1;
                    acc[mi][ni][3] *= rv1;
                }
            }
        }
    }

    // ---------------- epilogue: process 256-row tile in two 128-row halves ----------------
    if (MODE == 2) {
        float bn_s = 0.f, bn_s2 = 0.f;
        #pragma unroll
        for (int h = 0; h < 2; h++) {
            __syncthreads();
            if ((warp_m >> 1) == h) {
                #pragma unroll
                for (int mi = 0; mi < 4; mi++)
                    #pragma unroll
                    for (int ni = 0; ni < 8; ni++) {
                        int r0 = (warp_m & 1) * 64 + mi * 16 + gID;
                        int c  = warp_n * 64 + ni * 8 + t4 * 2;
                        Ts[c * 132 + r0]           = acc[mi][ni][0];
                        Ts[(c + 1) * 132 + r0]     = acc[mi][ni][1];
                        Ts[c * 132 + r0 + 8]       = acc[mi][ni][2];
                        Ts[(c + 1) * 132 + r0 + 8] = acc[mi][ni][3];
                    }
            }
            __syncthreads();
            int nbase = n0 + h * 128;
            int b = nbase >> 12, hw0 = nbase & 4095;
            float* ybase = g_yraw + (size_t)b * (256 * 4096) + hw0;
            #pragma unroll
            for (int p = 0; p < 16; p++) {
                int q = p * 256 + tid;
                int o = q >> 5, seg = q & 31;
                float4 v = *(float4*)&Ts[o * 132 + seg * 4];
                *(float4*)(ybase + (size_t)(m0 + o) * 4096 + seg * 4) = v;
            }
            {
                int o = tid >> 1, nh = tid & 1;
                #pragma unroll 16
                for (int jj = 0; jj < 64; jj++) {
                    float v = Ts[o * 132 + nh * 64 + jj];
                    bn_s += v; bn_s2 += v * v;
                }
            }
        }
        __syncthreads();
        red1[tid] = bn_s; red2[tid] = bn_s2;
        __syncthreads();
        if (tid < 128) {
            g_sp [blockIdx.y * 256 + m0 + tid] = red1[2 * tid] + red1[2 * tid + 1];
            g_sp2[blockIdx.y * 256 + m0 + tid] = red2[2 * tid] + red2[2 * tid + 1];
        }
        return;
    }

    // MODE 1
    float colacc = 0.f;
    #pragma unroll
    for (int h = 0; h < 2; h++) {
        __syncthreads();
        if ((warp_m >> 1) == h) {
            #pragma unroll
            for (int mi = 0; mi < 4; mi++)
                #pragma unroll
                for (int ni = 0; ni < 8; ni++) {
                    int r0 = (warp_m & 1) * 64 + mi * 16 + gID;
                    int c  = warp_n * 64 + ni * 8 + t4 * 2;
                    Ts[r0 * 132 + c]           = expf(acc[mi][ni][0]);
                    Ts[r0 * 132 + c + 1]       = expf(acc[mi][ni][1]);
                    Ts[(r0 + 8) * 132 + c]     = expf(acc[mi][ni][2]);
                    Ts[(r0 + 8) * 132 + c + 1] = expf(acc[mi][ni][3]);
                }
        }
        __syncthreads();
        // row partial sums over this 128-col tile
        {
            int r = tid >> 1, rh = tid & 1;
            float s = 0.f;
            #pragma unroll 16
            for (int jj = 0; jj < 64; jj++) s += Ts[r * 132 + rh * 64 + jj];
            red1[tid] = s;
        }
        // column partial accumulate (64-row strip per thread, both halves)
        {
            int c = tid & 127, rq = tid >> 7;
            #pragma unroll 16
            for (int rr = 0; rr < 64; rr++) colacc += Ts[(rq * 64 + rr) * 132 + c];
        }
        // pack bf16 hi/lo, coalesced
        #pragma unroll
        for (int p = 0; p < 8; p++) {
            int cid = p * 256 + tid;
            int r = cid >> 4, cc = cid & 15;
            uint32_t hp[4], lp[4];
            #pragma unroll
            for (int jj = 0; jj < 4; jj++) {
                float v0 = Ts[r * 132 + cc * 8 + 2 * jj];
                float v1 = Ts[r * 132 + cc * 8 + 2 * jj + 1];
                __nv_bfloat16 h0, l0, h1, l1;
                split_bf(v0, h0, l0);
                split_bf(v1, h1, l1);
                hp[jj] = pack_bf2(h0, h1);
                lp[jj] = pack_bf2(l0, l1);
            }
            size_t off = (size_t)(n0 + h * 128 + r) * 512 + m0 + cc * 8;
            *(uint4*)(g_E_hi + off) = *(uint4*)hp;
            *(uint4*)(g_E_lo + off) = *(uint4*)lp;
        }
        __syncthreads();
        if (tid < 128)
            g_rowpart[blockIdx.x][n0 + h * 128 + tid] = red1[2 * tid] + red1[2 * tid + 1];
    }
    __syncthreads();
    red2[tid] = colacc;
    __syncthreads();
    if (tid < 128)
        g_cp[blockIdx.y * 512 + m0 + tid] = red2[tid] + red2[tid + 128];
}

// ---------------- rinv from row partials ----------------
__global__ void k_rinv() {
    int n = blockIdx.x * 256 + threadIdx.x;
    g_rinv[n] = 1.0f / (g_rowpart[0][n] + g_rowpart[1][n] + g_rowpart[2][n] + g_rowpart[3][n]);
}

// ---------------- cinv from column partials ----------------
__global__ void k_colfin() {
    int m = threadIdx.x;   // 512 threads, 1 block
    float s = 0.f;
    #pragma unroll 8
    for (int y = 0; y < 256; y++) s += g_cp[y * 512 + m];
    g_cinv[m] = 1.0f / s;
}

// ---------------- write both softmax outputs ----------------
__global__ void k_soft(float* __restrict__ ssq, float* __restrict__ ssm) {
    size_t idx = (size_t)blockIdx.x * 256 + threadIdx.x;
    size_t e0 = idx * 8;
    int n = (int)(e0 >> 9);
    int m = (int)(e0 & 511);
    uint4 hv = *(const uint4*)(g_E_hi + e0);
    uint4 lv = *(const uint4*)(g_E_lo + e0);
    float rv = g_rinv[n];
    const __nv_bfloat162* hp = (const __nv_bfloat162*)&hv;
    const __nv_bfloat162* lp = (const __nv_bfloat162*)&lv;
    float eo[8];
    #pragma unroll
    for (int i = 0; i < 4; i++) {
        float2 h2 = __bfloat1622float2(hp[i]);
        float2 l2 = __bfloat1622float2(lp[i]);
        eo[2 * i]     = h2.x + l2.x;
        eo[2 * i + 1] = h2.y + l2.y;
    }
    float4 sm0 = make_float4(eo[0] * rv, eo[1] * rv, eo[2] * rv, eo[3] * rv);
    float4 sm1 = make_float4(eo[4] * rv, eo[5] * rv, eo[6] * rv, eo[7] * rv);
    float4 sq0 = make_float4(eo[0] * g_cinv[m], eo[1] * g_cinv[m + 1],
                             eo[2] * g_cinv[m + 2], eo[3] * g_cinv[m + 3]);
    float4 sq1 = make_float4(eo[4] * g_cinv[m + 4], eo[5] * g_cinv[m + 5],
                             eo[6] * g_cinv[m + 6], eo[7] * g_cinv[m + 7]);
    *(float4*)(ssm + e0) = sm0;
    *(float4*)(ssm + e0 + 4) = sm1;
    *(float4*)(ssq + e0) = sq0;
    *(float4*)(ssq + e0 + 4) = sq1;
}

// ---------------- BN statistics finalize from partials ----------------
__global__ void k_statfin() {
    int o = threadIdx.x;   // 256 threads, 1 block
    float s = 0.f, s2 = 0.f;
    #pragma unroll 8
    for (int y = 0; y < 256; y++) {
        s  += g_sp [y * 256 + o];
        s2 += g_sp2[y * 256 + o];
    }
    float mean = s * (1.0f / 65536.0f);
    float var  = s2 * (1.0f / 65536.0f) - mean * mean;
    g_mean[o] = mean;
    g_rstd[o] = rsqrtf(var + 1e-5f);
}

// ---------------- BN affine + ReLU ----------------
__global__ void k_bn(const float* __restrict__ gamma, const float* __restrict__ beta,
                     float* __restrict__ yout) {
    int idx = blockIdx.x * blockDim.x + threadIdx.x;
    size_t e0 = (size_t)idx * 4;
    int o = (int)((e0 >> 12) & 255);
    float4 v = *(const float4*)(g_yraw + e0);
    float sc = g_rstd[o] * gamma[o];
    float sh = beta[o] - g_mean[o] * sc;
    float4 r = make_float4(fmaxf(v.x * sc + sh, 0.f), fmaxf(v.y * sc + sh, 0.f),
                           fmaxf(v.z * sc + sh, 0.f), fmaxf(v.w * sc + sh, 0.f));
    *(float4*)(yout + e0) = r;
}

// ---------------- launch ----------------
extern "C" void kernel_launch(void* const* d_in, const int* in_sizes, int n_in,
                              void* d_out, int out_size) {
    const float* query = (const float*)d_in[0];
    const float* mem   = (const float*)d_in[1];
    const float* convw = (const float*)d_in[2];
    const float* gamma = (const float*)d_in[3];
    const float* beta  = (const float*)d_in[4];

    float* out = (float*)d_out;
    float* y_out   = out;
    float* ssq_out = out + 16777216;
    float* ssm_out = out + 16777216 + 33554432;

    cudaFuncSetAttribute(k_gemm_mma<1>, cudaFuncAttributeMaxDynamicSharedMemorySize, SMEM_DYN);
    cudaFuncSetAttribute(k_gemm_mma<2>, cudaFuncAttributeMaxDynamicSharedMemorySize, SMEM_DYN);

    k_norm   <<<2048, 256>>>(query);
    k_prep   <<<512, 256>>>(mem, convw);
    k_compP  <<<dim3(2, 32), 256>>>(convw);
    k_gemm_mma<1><<<dim3(4, 256), 256, SMEM_DYN>>>();
    k_rinv   <<<256, 256>>>();
    k_colfin <<<1, 512>>>();
    k_soft   <<<16384, 256>>>(ssq_out, ssm_out);
    k_gemm_mma<2><<<dim3(2, 256), 256, SMEM_DYN>>>();
    k_statfin<<<1, 256>>>();
    k_bn     <<<16384, 256>>>(gamma, beta, y_out);
}